// round 2
// baseline (speedup 1.0000x reference)
#include <cuda_runtime.h>
#include <cstdint>
#include <cstddef>

// ---------------------------------------------------------------------------
// PointSampler: jax threefry masked random-permutation sampling.
//   x [B,C,H,W] f32, mask [B,1,H,W] f32, k=4096
//   out = concat( samples[B,k,C], b_idx[B,k], h_idx[B,k], w_idx[B,k] ) f32
// Kernel 1 (select): threefry keys + counting-sort rank + idx outputs + inverse
//                    slot map.   Kernel 2 (gather): coalesced plane sweep.
// ---------------------------------------------------------------------------

constexpr int B = 16, C = 256, H = 128, W = 128;
constexpr int L = H * W;        // 16384
constexpr int K = 4096;
constexpr int NBIN = 16385;
constexpr int SEL_SMEM = L * 8 + 16386 * 4 + 1024 * 4;     // pairs + hist + part

constexpr int CT = 8;                                       // c-tile for gather
constexpr int GATHER_SMEM = L * 2 + CT * K * 4;             // slot + stage = 160KB

__device__ uint32_t g_pos[B * K];      // rank -> flat position (fallback path)
__device__ uint16_t g_slot[B * L];     // pos -> rank (0xFFFF = not selected)
__device__ int      g_counts[B];

// ---- jax threefry2x32 (20 rounds), partitionable mode ---------------------
__device__ __forceinline__ uint32_t jax_bits(uint32_t n) {
    uint32_t k0 = 0u, k1 = 42u;
    uint32_t ks2 = k0 ^ k1 ^ 0x1BD11BDAu;
    uint32_t x0 = 0u + k0, x1 = n + k1;
#define TF_RND(r) { x0 += x1; x1 = __funnelshift_l(x1, x1, (r)); x1 ^= x0; }
    TF_RND(13) TF_RND(15) TF_RND(26) TF_RND(6)
    x0 += k1;  x1 += ks2 + 1u;
    TF_RND(17) TF_RND(29) TF_RND(16) TF_RND(24)
    x0 += ks2; x1 += k0 + 2u;
    TF_RND(13) TF_RND(15) TF_RND(26) TF_RND(6)
    x0 += k0;  x1 += k1 + 3u;
    TF_RND(17) TF_RND(29) TF_RND(16) TF_RND(24)
    x0 += k1;  x1 += ks2 + 4u;
    TF_RND(13) TF_RND(15) TF_RND(26) TF_RND(6)
    x0 += ks2; x1 += k0 + 5u;
#undef TF_RND
    return x0 ^ x1;
}

// ---- kernel 1: fused keys + per-batch stable rank + idx + slot map --------
__global__ __launch_bounds__(1024, 1) void select_kernel(
        const float* __restrict__ mask, float* __restrict__ out, int out_size) {
    extern __shared__ unsigned char sm[];
    uint64_t* pairs = (uint64_t*)sm;                               // 16384*8
    uint32_t* hist  = (uint32_t*)(sm + (size_t)L * 8);             // 16386*4
    uint32_t* part  = (uint32_t*)(sm + (size_t)L * 8 + 16386 * 4); // 1024*4
    uint32_t* rankpos = hist;                                      // reuse after scatter

    const int b = blockIdx.x;
    const int t = threadIdx.x;

    // init inverse slot map for this batch (u32-wide stores)
    {
        uint32_t* sl = (uint32_t*)(g_slot + (size_t)b * L);
        for (int i = t; i < L / 2; i += 1024) sl[i] = 0xFFFFFFFFu;
    }

    // compute sort keys inline: (mantissa-prefix key << 14) | flat position
    uint64_t keys[16];
#pragma unroll
    for (int i = 0; i < 16; i++) {
        int l = t + i * 1024;
        uint32_t n = (uint32_t)(b * L + l);
        uint32_t bits = jax_bits(n);
        bool masked = mask[n] > 0.5f;
        uint32_t mkey = masked ? (bits >> 9) : 0x800000u;
        keys[i] = (((uint64_t)mkey) << 14) | (uint64_t)l;
    }

    for (int i = t; i < NBIN; i += 1024) hist[i] = 0u;
    __syncthreads();

#pragma unroll
    for (int i = 0; i < 16; i++)
        atomicAdd(&hist[(uint32_t)(keys[i] >> 23)], 1u);
    __syncthreads();

    // exclusive scan over 16385 bins
    const int start = t * 16;
    const int cnt = (t == 1023) ? 17 : 16;
    uint32_t s = 0;
    for (int i = 0; i < cnt; i++) s += hist[start + i];
    part[t] = s;
    __syncthreads();
    for (int off = 1; off < 1024; off <<= 1) {
        uint32_t v = part[t];
        uint32_t a = (t >= off) ? part[t - off] : 0u;
        __syncthreads();
        part[t] = v + a;
        __syncthreads();
    }
    uint32_t run = (t == 0) ? 0u : part[t - 1];
    for (int i = 0; i < cnt; i++) {
        uint32_t h = hist[start + i];
        hist[start + i] = run;
        run += h;
    }
    __syncthreads();
    int count = (int)hist[16384];
    if (t == 0) g_counts[b] = count;
    __syncthreads();

    // counting-sort scatter
#pragma unroll
    for (int i = 0; i < 16; i++) {
        uint32_t slot = atomicAdd(&hist[(uint32_t)(keys[i] >> 23)], 1u);
        pairs[slot] = keys[i];
    }
    __syncthreads();

    // final rank = bin base + #smaller within bin (avg 1 element/bin)
    for (int sI = t; sI < L; sI += 1024) {
        uint64_t kv = pairs[sI];
        uint32_t mk = (uint32_t)(kv >> 14);
        if (mk >= 0x800000u) continue;
        uint32_t bn = (uint32_t)(kv >> 23);
        int g = sI;
        while (g > 0 && (uint32_t)(pairs[g - 1] >> 23) == bn) g--;
        int r = 0;
        for (int u = g; u < L; u++) {
            uint64_t pk = pairs[u];
            if ((uint32_t)(pk >> 23) != bn) break;
            if (pk < kv) r++;
        }
        int rank = g + r;
        if (rank < K) {
            uint32_t p = (uint32_t)(kv & (uint64_t)(L - 1));
            g_pos[b * K + rank] = p;
            rankpos[rank] = p;                     // smem copy for idx writes
            if (rank < count) g_slot[(size_t)b * L + p] = (uint16_t)rank;
        }
    }
    __syncthreads();

    // (b, h, w) index outputs
    size_t off = (size_t)B * K * C;
    if ((size_t)out_size >= off + 3u * (size_t)(B * K)) {
        for (int j = t; j < K; j += 1024) {
            int eff = (j < count) ? j : (j % count);
            uint32_t p = rankpos[eff];
            size_t i = (size_t)b * K + j;
            out[off + i] = (float)b;
            out[off + (size_t)(B * K) + i] = (float)(p >> 7);
            out[off + 2u * (size_t)(B * K) + i] = (float)(p & (W - 1));
        }
    }
}

// ---- kernel 2: coalesced plane-sweep gather -------------------------------
__global__ __launch_bounds__(512, 1) void gather_kernel(
        const float* __restrict__ x, float* __restrict__ out) {
    extern __shared__ unsigned char sm[];
    uint16_t* slot = (uint16_t*)sm;                        // 16384 u16 = 32KB
    float* stage = (float*)(sm + (size_t)L * 2);           // [CT][K] = 128KB

    const int b = blockIdx.y;
    const int c0 = blockIdx.x * CT;
    const int t = threadIdx.x;
    const int cb = g_counts[b];

    // load inverse slot map (coalesced u32)
    {
        const uint32_t* gs = (const uint32_t*)(g_slot + (size_t)b * L);
        uint32_t* ss = (uint32_t*)slot;
        for (int i = t; i < L / 2; i += 512) ss[i] = gs[i];
    }
    __syncthreads();

    // sweep: 64 threads per plane, fully coalesced float4 reads
    const int ci = t >> 6;          // 0..7
    const int ii = t & 63;
    const float4* plane = (const float4*)(x + ((size_t)(b * C + c0 + ci)) * (size_t)L);
    float* st = stage + (size_t)ci * K;

    for (int s0 = 0; s0 < 64; s0 += 8) {
        float4 v[8];
#pragma unroll
        for (int u = 0; u < 8; u++)
            v[u] = __ldg(&plane[ii + (s0 + u) * 64]);
#pragma unroll
        for (int u = 0; u < 8; u++) {
            int pos = (ii + (s0 + u) * 64) * 4;
            uint32_t j0 = slot[pos + 0];
            uint32_t j1 = slot[pos + 1];
            uint32_t j2 = slot[pos + 2];
            uint32_t j3 = slot[pos + 3];
            if (j0 != 0xFFFFu) st[j0] = v[u].x;
            if (j1 != 0xFFFFu) st[j1] = v[u].y;
            if (j2 != 0xFFFFu) st[j2] = v[u].z;
            if (j3 != 0xFFFFu) st[j3] = v[u].w;
        }
    }
    __syncthreads();

    // write-out: coalesced float4 stores, c-transposed reads (conflict-free)
    int jmax = (cb < K) ? cb : K;
#pragma unroll
    for (int r = 0; r < 8; r++) {
        int j = t + r * 512;
        if (j < jmax) {
            float4 a, d;
            a.x = stage[0 * K + j]; a.y = stage[1 * K + j];
            a.z = stage[2 * K + j]; a.w = stage[3 * K + j];
            d.x = stage[4 * K + j]; d.y = stage[5 * K + j];
            d.z = stage[6 * K + j]; d.w = stage[7 * K + j];
            float4* o = (float4*)(out + ((size_t)b * K + j) * (size_t)C + c0);
            o[0] = a;
            o[1] = d;
        }
    }

    // fallback for wrapped samples (count < K) — never executes in practice
    for (int j = cb + t; j < K; j += 512) {
        uint32_t p = g_pos[b * K + (j % cb)];
        for (int cc = 0; cc < CT; cc++)
            out[((size_t)b * K + j) * (size_t)C + c0 + cc] =
                __ldg(&x[((size_t)(b * C + c0 + cc)) * (size_t)L + p]);
    }
}

extern "C" void kernel_launch(void* const* d_in, const int* in_sizes, int n_in,
                              void* d_out, int out_size) {
    const float* x = (const float*)d_in[0];
    int mi = n_in - 1;
    for (int i = 1; i < n_in; i++)
        if (in_sizes[i] == B * L) { mi = i; break; }
    const float* mask = (const float*)d_in[mi];
    float* out = (float*)d_out;

    cudaFuncSetAttribute(select_kernel,
                         cudaFuncAttributeMaxDynamicSharedMemorySize, SEL_SMEM);
    cudaFuncSetAttribute(gather_kernel,
                         cudaFuncAttributeMaxDynamicSharedMemorySize, GATHER_SMEM);

    select_kernel<<<B, 1024, SEL_SMEM>>>(mask, out, out_size);
    dim3 gg(C / CT, B);
    gather_kernel<<<gg, 512, GATHER_SMEM>>>(x, out);
}

// round 3
// speedup vs baseline: 1.3763x; 1.3763x over previous
#include <cuda_runtime.h>
#include <cstdint>
#include <cstddef>

// ---------------------------------------------------------------------------
// PointSampler: jax threefry masked random-permutation sampling.
//   x [B,C,H,W] f32, mask [B,1,H,W] f32, k=4096
//   out = concat( samples[B,k,C], b_idx[B,k], h_idx[B,k], w_idx[B,k] ) f32
//   K0 keys (full chip)  ->  K1 select (1 CTA/batch)  ->  K2 gather (compact)
// ---------------------------------------------------------------------------

constexpr int B = 16, C = 256, H = 128, W = 128;
constexpr int L = H * W;        // 16384
constexpr int K = 4096;
constexpr int NBIN = 16385;

// select smem: pairs(128K) + hist(64.1K) + part(4K)
constexpr int SEL_SMEM = L * 8 + 16386 * 4 + 1024 * 4;

// gather smem: sel list 16KB + stage 8 x 4100 f32 (padded stride, no bank conflicts)
constexpr int CT = 8;
constexpr int STG = 4100;
constexpr int GATHER_SMEM = K * 4 + CT * STG * 4;

__device__ uint64_t g_keys[B * L];
__device__ uint32_t g_pos[B * K];      // rank -> flat position
__device__ uint32_t g_sel[B * K];      // pos-sorted: (pos<<16) | rank
__device__ int      g_counts[B];

// ---- jax threefry2x32 (20 rounds), partitionable mode ---------------------
__device__ __forceinline__ uint32_t jax_bits(uint32_t n) {
    uint32_t k0 = 0u, k1 = 42u;
    uint32_t ks2 = k0 ^ k1 ^ 0x1BD11BDAu;
    uint32_t x0 = k0, x1 = n + k1;
#define TF_RND(r) { x0 += x1; x1 = __funnelshift_l(x1, x1, (r)); x1 ^= x0; }
    TF_RND(13) TF_RND(15) TF_RND(26) TF_RND(6)
    x0 += k1;  x1 += ks2 + 1u;
    TF_RND(17) TF_RND(29) TF_RND(16) TF_RND(24)
    x0 += ks2; x1 += k0 + 2u;
    TF_RND(13) TF_RND(15) TF_RND(26) TF_RND(6)
    x0 += k0;  x1 += k1 + 3u;
    TF_RND(17) TF_RND(29) TF_RND(16) TF_RND(24)
    x0 += k1;  x1 += ks2 + 4u;
    TF_RND(13) TF_RND(15) TF_RND(26) TF_RND(6)
    x0 += ks2; x1 += k0 + 5u;
#undef TF_RND
    return x0 ^ x1;
}

// ---- kernel 0: sort keys, full chip ---------------------------------------
__global__ void keys_kernel(const float* __restrict__ mask) {
    int n = blockIdx.x * blockDim.x + threadIdx.x;
    if (n >= B * L) return;
    uint32_t bits = jax_bits((uint32_t)n);
    bool masked = mask[n] > 0.5f;
    uint32_t mkey = masked ? (bits >> 9) : 0x800000u;
    uint32_t l = (uint32_t)n & (uint32_t)(L - 1);
    g_keys[n] = (((uint64_t)mkey) << 14) | (uint64_t)l;
}

// ---- kernel 1: per-batch stable rank + compact sel list + idx out ---------
__global__ __launch_bounds__(1024, 1) void select_kernel(
        float* __restrict__ out, int out_size) {
    extern __shared__ unsigned char sm[];
    uint64_t* pairs = (uint64_t*)sm;                               // [0,128K)
    uint32_t* hist  = (uint32_t*)(sm + (size_t)L * 8);             // 16386 u32
    uint32_t* part  = (uint32_t*)(sm + (size_t)L * 8 + 16386 * 4); // 1024 u32
    uint32_t* rankpos = hist;                                      // [0,16KB) of hist
    uint16_t* slot_sm = (uint16_t*)(hist + K);                     // next 32KB of hist

    const int b = blockIdx.x;
    const int t = threadIdx.x;

    uint64_t keys[16];
#pragma unroll
    for (int i = 0; i < 16; i++)
        keys[i] = g_keys[b * L + t + i * 1024];

    for (int i = t; i < NBIN; i += 1024) hist[i] = 0u;
    __syncthreads();

#pragma unroll
    for (int i = 0; i < 16; i++)
        atomicAdd(&hist[(uint32_t)(keys[i] >> 23)], 1u);
    __syncthreads();

    // exclusive scan over 16385 bins
    const int start = t * 16;
    const int cnt = (t == 1023) ? 17 : 16;
    uint32_t s = 0;
    for (int i = 0; i < cnt; i++) s += hist[start + i];
    part[t] = s;
    __syncthreads();
    for (int off = 1; off < 1024; off <<= 1) {
        uint32_t v = part[t];
        uint32_t a = (t >= off) ? part[t - off] : 0u;
        __syncthreads();
        part[t] = v + a;
        __syncthreads();
    }
    uint32_t run = (t == 0) ? 0u : part[t - 1];
    for (int i = 0; i < cnt; i++) {
        uint32_t h = hist[start + i];
        hist[start + i] = run;
        run += h;
    }
    __syncthreads();
    int count = (int)hist[16384];
    if (t == 0) g_counts[b] = count;
    __syncthreads();

    // counting-sort scatter
#pragma unroll
    for (int i = 0; i < 16; i++) {
        uint32_t slt = atomicAdd(&hist[(uint32_t)(keys[i] >> 23)], 1u);
        pairs[slt] = keys[i];
    }
    __syncthreads();

    // hist region now reusable: rankpos[0..4095], slot_sm[16384] after it
    {
        uint32_t* ss = (uint32_t*)slot_sm;
        for (int i = t; i < L / 2; i += 1024) ss[i] = 0xFFFFFFFFu;
    }
    __syncthreads();

    // final rank = bin base + #smaller within bin
    for (int sI = t; sI < L; sI += 1024) {
        uint64_t kv = pairs[sI];
        uint32_t mk = (uint32_t)(kv >> 14);
        if (mk >= 0x800000u) continue;
        uint32_t bn = (uint32_t)(kv >> 23);
        int g = sI;
        while (g > 0 && (uint32_t)(pairs[g - 1] >> 23) == bn) g--;
        int r = 0;
        for (int u = g; u < L; u++) {
            uint64_t pk = pairs[u];
            if ((uint32_t)(pk >> 23) != bn) break;
            if (pk < kv) r++;
        }
        int rank = g + r;
        if (rank < K) {
            uint32_t p = (uint32_t)(kv & (uint64_t)(L - 1));
            g_pos[b * K + rank] = p;
            rankpos[rank] = p;
            slot_sm[p] = (uint16_t)rank;
        }
    }
    __syncthreads();

    // compact: pos-sorted (pos<<16)|rank for selected positions
    {
        const int p0 = t * 16;
        uint32_t c2 = 0;
#pragma unroll
        for (int i = 0; i < 16; i++)
            if (slot_sm[p0 + i] != 0xFFFFu) c2++;
        part[t] = c2;
        __syncthreads();
        for (int off = 1; off < 1024; off <<= 1) {
            uint32_t v = part[t];
            uint32_t a = (t >= off) ? part[t - off] : 0u;
            __syncthreads();
            part[t] = v + a;
            __syncthreads();
        }
        uint32_t base = part[t] - c2;
#pragma unroll
        for (int i = 0; i < 16; i++) {
            uint16_t rk = slot_sm[p0 + i];
            if (rk != 0xFFFFu)
                g_sel[b * K + (base++)] = ((uint32_t)(p0 + i) << 16) | (uint32_t)rk;
        }
    }

    // (b, h, w) index outputs
    size_t off = (size_t)B * K * C;
    if ((size_t)out_size >= off + 3u * (size_t)(B * K)) {
        for (int j = t; j < K; j += 1024) {
            int eff = (j < count) ? j : (j % count);
            uint32_t p = rankpos[eff];
            size_t i = (size_t)b * K + j;
            out[off + i] = (float)b;
            out[off + (size_t)(B * K) + i] = (float)(p >> 7);
            out[off + 2u * (size_t)(B * K) + i] = (float)(p & (W - 1));
        }
    }
}

// ---- kernel 2: compact-list gather ----------------------------------------
__global__ __launch_bounds__(1024, 1) void gather_kernel(
        const float* __restrict__ x, float* __restrict__ out) {
    extern __shared__ unsigned char sm[];
    uint32_t* sel = (uint32_t*)sm;                         // 4096 u32
    float* stage = (float*)(sm + (size_t)K * 4);           // [CT][STG]

    const int b = blockIdx.y;
    const int c0 = blockIdx.x * CT;
    const int t = threadIdx.x;
    const int cb = g_counts[b];
    const int nsel = (cb < K) ? cb : K;

    for (int i = t; i < K; i += 1024)
        sel[i] = g_sel[b * K + i];
    __syncthreads();

    // 128 threads per plane; sorted-pos loads share sectors
    const int ci = t >> 7;          // 0..7
    const int ii = t & 127;
    const float* plane = x + ((size_t)(b * C + c0 + ci)) * (size_t)L;
    float* st = stage + (size_t)ci * STG;

    for (int s0 = 0; s0 < 32; s0 += 8) {
        uint32_t e[8];
        float v[8];
#pragma unroll
        for (int u = 0; u < 8; u++) {
            int idx = ii + (s0 + u) * 128;
            e[u] = (idx < nsel) ? sel[idx] : 0xFFFF0000u;
        }
#pragma unroll
        for (int u = 0; u < 8; u++)
            if (e[u] != 0xFFFF0000u) v[u] = __ldg(&plane[e[u] >> 16]);
#pragma unroll
        for (int u = 0; u < 8; u++)
            if (e[u] != 0xFFFF0000u) st[e[u] & 0xFFFFu] = v[u];
    }
    __syncthreads();

    // write-out: warp = 4 ranks x 8 channels -> 32B contiguous per rank
    const int c = t & 7;
    const int jl = t >> 3;          // 0..127
#pragma unroll
    for (int r = 0; r < 32; r++) {
        int j = jl + r * 128;
        if (j < nsel)
            out[((size_t)b * K + j) * (size_t)C + c0 + c] = stage[(size_t)c * STG + j];
    }

    // wrap fallback (count < K) — no-op in practice
    for (int j = cb + t; j < K; j += 1024) {
        uint32_t p = g_pos[b * K + (j % cb)];
#pragma unroll
        for (int cc = 0; cc < CT; cc++)
            out[((size_t)b * K + j) * (size_t)C + c0 + cc] =
                __ldg(&x[((size_t)(b * C + c0 + cc)) * (size_t)L + p]);
    }
}

extern "C" void kernel_launch(void* const* d_in, const int* in_sizes, int n_in,
                              void* d_out, int out_size) {
    const float* x = (const float*)d_in[0];
    int mi = n_in - 1;
    for (int i = 1; i < n_in; i++)
        if (in_sizes[i] == B * L) { mi = i; break; }
    const float* mask = (const float*)d_in[mi];
    float* out = (float*)d_out;

    cudaFuncSetAttribute(select_kernel,
                         cudaFuncAttributeMaxDynamicSharedMemorySize, SEL_SMEM);
    cudaFuncSetAttribute(gather_kernel,
                         cudaFuncAttributeMaxDynamicSharedMemorySize, GATHER_SMEM);

    keys_kernel<<<(B * L + 511) / 512, 512>>>(mask);
    select_kernel<<<B, 1024, SEL_SMEM>>>(out, out_size);
    dim3 gg(C / CT, B);
    gather_kernel<<<gg, 1024, GATHER_SMEM>>>(x, out);
}